// round 1
// baseline (speedup 1.0000x reference)
#include <cuda_runtime.h>
#include <cstdint>

// ---------------------------------------------------------------------------
// RowLSTM: x(16,64,64,64), Wi(512,64,1,3), bi(512), Wh(512,128), bh(512)
// out: (16,128,64,64) fp32
//
// Phase 1: i2h[h][b][w][g] = conv1x3(x, Wi) + bi + bh   (GEMM M=65536,N=512,K=192)
// Phase 2: per (b,w) column independent LSTM scan over h (rows).
// ---------------------------------------------------------------------------

#define B_  16
#define C_  64
#define H_  64
#define W_  64
#define HID_ 128
#define G_  512   // 4*HID

// scratch: 64*16*64*512 floats = 134MB
static __device__ float g_i2h[(size_t)H_ * B_ * W_ * G_];

// ---------------------------------------------------------------------------
// Kernel A: i2h. One block per (b,h). 512 threads.
// thread tid: gg = tid&63 -> gates [gg*8, gg*8+8); wg = tid>>6 -> w [wg*8, wg*8+8)
// ---------------------------------------------------------------------------
__global__ void __launch_bounds__(512, 1)
i2h_kernel(const float* __restrict__ x, const float* __restrict__ Wi,
           const float* __restrict__ bi, const float* __restrict__ bh)
{
    const int b = blockIdx.x & 15;
    const int h = blockIdx.x >> 4;
    const int tid = threadIdx.x;

    __shared__ float xs[C_][68];   // [c][ww], ww = w+1 (zero pad at 0 and 65)
    __shared__ float ws[12][G_];   // [kk][g] chunk of Wi, k = kc*12 + kk, k=(c*3+kw)

    // fill x tile (coalesced: consecutive tid -> consecutive w)
    for (int idx = tid; idx < C_ * W_; idx += 512) {
        int c = idx >> 6, w = idx & 63;
        xs[c][w + 1] = x[((((size_t)b * C_) + c) * H_ + h) * W_ + w];
    }
    if (tid < C_) { xs[tid][0] = 0.f; xs[tid][65] = 0.f; xs[tid][66] = 0.f; xs[tid][67] = 0.f; }
    __syncthreads();

    const int g0 = (tid & 63) * 8;
    const int w0 = (tid >> 6) * 8;

    float acc[8][8];   // [gate_i][w_j]
#pragma unroll
    for (int i = 0; i < 8; i++)
#pragma unroll
        for (int j = 0; j < 8; j++) acc[i][j] = 0.f;

    for (int kc = 0; kc < 16; kc++) {
        // stage Wi chunk: ws[kk][g] = Wi[g*192 + kc*12 + kk]
#pragma unroll
        for (int j = 0; j < 12; j++)
            ws[j][tid] = Wi[(size_t)tid * 192 + kc * 12 + j];
        __syncthreads();

#pragma unroll
        for (int cc = 0; cc < 4; cc++) {
            const int c = kc * 4 + cc;
            const float4* xp = reinterpret_cast<const float4*>(&xs[c][w0]);
            float4 xa = xp[0], xb = xp[1], xc = xp[2];
            float xr[12] = {xa.x, xa.y, xa.z, xa.w,
                            xb.x, xb.y, xb.z, xb.w,
                            xc.x, xc.y, xc.z, xc.w};
#pragma unroll
            for (int kw = 0; kw < 3; kw++) {
                const float4* wp = reinterpret_cast<const float4*>(&ws[cc * 3 + kw][g0]);
                float4 wa = wp[0], wb = wp[1];
                float wv[8] = {wa.x, wa.y, wa.z, wa.w, wb.x, wb.y, wb.z, wb.w};
#pragma unroll
                for (int i = 0; i < 8; i++)
#pragma unroll
                    for (int j = 0; j < 8; j++)
                        acc[i][j] = fmaf(wv[i], xr[j + kw], acc[i][j]);
            }
        }
        __syncthreads();
    }

    // fused bias (bi + bh) and store to g_i2h[h][b][w][g]
    float bias[8];
#pragma unroll
    for (int i = 0; i < 8; i++) bias[i] = bi[g0 + i] + bh[g0 + i];

    const size_t obase = ((((size_t)h * B_ + b) * W_) + w0) * G_ + g0;
#pragma unroll
    for (int j = 0; j < 8; j++) {
        float4 v0 = make_float4(acc[0][j] + bias[0], acc[1][j] + bias[1],
                                acc[2][j] + bias[2], acc[3][j] + bias[3]);
        float4 v1 = make_float4(acc[4][j] + bias[4], acc[5][j] + bias[5],
                                acc[6][j] + bias[6], acc[7][j] + bias[7]);
        *reinterpret_cast<float4*>(&g_i2h[obase + (size_t)j * G_])     = v0;
        *reinterpret_cast<float4*>(&g_i2h[obase + (size_t)j * G_ + 4]) = v1;
    }
}

// ---------------------------------------------------------------------------
// Kernel B: recurrent scan. 128 blocks = (b, w-group of 8 cols), 512 threads.
// thread t owns gate row t; Wh streamed from L2 (float4), reused over 8 cols.
// ---------------------------------------------------------------------------
__device__ __forceinline__ float sigmf(float v) {
    return __fdividef(1.0f, 1.0f + __expf(-v));
}
__device__ __forceinline__ float tanhf_(float v) {
    return __fdividef(2.0f, 1.0f + __expf(-2.0f * v)) - 1.0f;
}

__global__ void __launch_bounds__(512, 1)
rec_kernel(const float* __restrict__ Wh, float* __restrict__ out)
{
    const int b  = blockIdx.x >> 3;
    const int w0 = (blockIdx.x & 7) * 8;
    const int t  = threadIdx.x;

    __shared__ float hbuf[8][HID_];   // [col][d]
    __shared__ float cbuf[8][HID_];
    __shared__ float gbuf[8][G_];     // [col][gate]

    for (int p = t; p < 8 * HID_; p += 512) {
        (&hbuf[0][0])[p] = 0.f;
        (&cbuf[0][0])[p] = 0.f;
    }
    __syncthreads();

    const float4* __restrict__ Wh4 = reinterpret_cast<const float4*>(Wh) + (size_t)t * 32;

    for (int row = 0; row < H_; row++) {
        // init with i2h (already includes bi+bh)
        const float* gp = g_i2h + ((((size_t)row * B_ + b) * W_) + w0) * G_ + t;
        float acc[8];
#pragma unroll
        for (int col = 0; col < 8; col++) acc[col] = gp[(size_t)col * G_];

        // gates += Wh[t][:] . h[col][:]
#pragma unroll
        for (int k4 = 0; k4 < 32; k4 += 4) {
            float4 wv0 = Wh4[k4 + 0];
            float4 wv1 = Wh4[k4 + 1];
            float4 wv2 = Wh4[k4 + 2];
            float4 wv3 = Wh4[k4 + 3];
#pragma unroll
            for (int col = 0; col < 8; col++) {
                const float4* hp = reinterpret_cast<const float4*>(&hbuf[col][k4 * 4]);
                float4 h0 = hp[0], h1 = hp[1], h2 = hp[2], h3 = hp[3];
                float a = acc[col];
                a = fmaf(wv0.x, h0.x, a); a = fmaf(wv0.y, h0.y, a);
                a = fmaf(wv0.z, h0.z, a); a = fmaf(wv0.w, h0.w, a);
                a = fmaf(wv1.x, h1.x, a); a = fmaf(wv1.y, h1.y, a);
                a = fmaf(wv1.z, h1.z, a); a = fmaf(wv1.w, h1.w, a);
                a = fmaf(wv2.x, h2.x, a); a = fmaf(wv2.y, h2.y, a);
                a = fmaf(wv2.z, h2.z, a); a = fmaf(wv2.w, h2.w, a);
                a = fmaf(wv3.x, h3.x, a); a = fmaf(wv3.y, h3.y, a);
                a = fmaf(wv3.z, h3.z, a); a = fmaf(wv3.w, h3.w, a);
                acc[col] = a;
            }
        }
#pragma unroll
        for (int col = 0; col < 8; col++) gbuf[col][t] = acc[col];
        __syncthreads();

        // pointwise LSTM update: 1024 (col,d) pairs by 512 threads
#pragma unroll
        for (int pp = 0; pp < 2; pp++) {
            int p   = t + pp * 512;
            int col = p >> 7;
            int d   = p & 127;
            float ig = gbuf[col][d];
            float fg = gbuf[col][HID_ + d];
            float og = gbuf[col][2 * HID_ + d];
            float gg = gbuf[col][3 * HID_ + d];
            float cv = sigmf(fg) * cbuf[col][d] + sigmf(ig) * tanhf_(gg);
            float hv = sigmf(og) * tanhf_(cv);
            cbuf[col][d] = cv;
            hbuf[col][d] = hv;
        }
        __syncthreads();

        // batched output write: out[b][d][row][w0..w0+8)
        if (t < HID_) {
            int d = t;
            float4 v0 = make_float4(hbuf[0][d], hbuf[1][d], hbuf[2][d], hbuf[3][d]);
            float4 v1 = make_float4(hbuf[4][d], hbuf[5][d], hbuf[6][d], hbuf[7][d]);
            float* op = out + ((((size_t)b * HID_ + d) * H_) + row) * W_ + w0;
            *reinterpret_cast<float4*>(op)     = v0;
            *reinterpret_cast<float4*>(op + 4) = v1;
        }
        __syncthreads();   // protect hbuf before next pointwise overwrites; dot reads are safe
    }
}

// ---------------------------------------------------------------------------
extern "C" void kernel_launch(void* const* d_in, const int* in_sizes, int n_in,
                              void* d_out, int out_size)
{
    (void)in_sizes; (void)n_in; (void)out_size;
    const float* x  = (const float*)d_in[0];
    const float* Wi = (const float*)d_in[1];
    const float* bi = (const float*)d_in[2];
    const float* Wh = (const float*)d_in[3];
    const float* bh = (const float*)d_in[4];
    float* out = (float*)d_out;

    i2h_kernel<<<B_ * H_, 512>>>(x, Wi, bi, bh);
    rec_kernel<<<B_ * (W_ / 8), 512>>>(Wh, out);
}